// round 6
// baseline (speedup 1.0000x reference)
#include <cuda_runtime.h>
#include <cuda_fp16.h>
#include <cstdint>

#define N_PTS 8192
#define DIMK  512
#define KNN   10
#define NTILE (N_PTS / 128)      // 64 column tiles per row

// Static device scratch (no runtime allocation allowed)
__device__ float  g_sq[N_PTS];
__device__ __half g_xhi[(size_t)N_PTS * DIMK];     // 8 MB
__device__ __half g_xlo[(size_t)N_PTS * DIMK];     // 8 MB
// Per-(row, tile) top-10 candidates, key = (d2_bits<<32)|col : 42 MB
__device__ unsigned long long g_cand[(size_t)N_PTS * NTILE * KNN];

// ---------------------------------------------------------------------------
// Kernel 1: fused prep — fp16 2-split of x AND fp64 squared norms.
// ---------------------------------------------------------------------------
__global__ void __launch_bounds__(256) prep_kernel(const float* __restrict__ x) {
    int row  = blockIdx.x * 8 + (threadIdx.x >> 5);
    int lane = threadIdx.x & 31;
    const float4* xr = (const float4*)(x + (size_t)row * DIMK);
    double s = 0.0;
#pragma unroll
    for (int t = 0; t < 4; t++) {
        int e = lane + t * 32;
        float4 v = xr[e];
        __half h[4], l[4];
        h[0] = __float2half_rn(v.x);  l[0] = __float2half_rn(v.x - __half2float(h[0]));
        h[1] = __float2half_rn(v.y);  l[1] = __float2half_rn(v.y - __half2float(h[1]));
        h[2] = __float2half_rn(v.z);  l[2] = __float2half_rn(v.z - __half2float(h[2]));
        h[3] = __float2half_rn(v.w);  l[3] = __float2half_rn(v.w - __half2float(h[3]));
        *(uint2*)&g_xhi[(size_t)row * DIMK + e * 4] = *(uint2*)h;
        *(uint2*)&g_xlo[(size_t)row * DIMK + e * 4] = *(uint2*)l;
        s += (double)v.x * v.x + (double)v.y * v.y
           + (double)v.z * v.z + (double)v.w * v.w;
    }
#pragma unroll
    for (int o = 16; o; o >>= 1)
        s += __shfl_xor_sync(0xFFFFFFFFu, s, o);
    if (lane == 0) g_sq[row] = (float)s;
}

// ---------------------------------------------------------------------------
// HMMA helpers (mma.sync path — tcgen05 is not reachable from compute_103 PTX)
// ---------------------------------------------------------------------------
__device__ __forceinline__ void ldsm4_addr(uint32_t& r0, uint32_t& r1,
                                           uint32_t& r2, uint32_t& r3, uint32_t a) {
    asm volatile("ldmatrix.sync.aligned.m8n8.x4.shared.b16 {%0,%1,%2,%3}, [%4];"
                 : "=r"(r0), "=r"(r1), "=r"(r2), "=r"(r3) : "r"(a));
}
__device__ __forceinline__ void ldsm2_addr(uint32_t& r0, uint32_t& r1, uint32_t a) {
    asm volatile("ldmatrix.sync.aligned.m8n8.x2.shared.b16 {%0,%1}, [%2];"
                 : "=r"(r0), "=r"(r1) : "r"(a));
}
__device__ __forceinline__ void mma16816(float c[4], const uint32_t a[4],
                                         const uint32_t b[2]) {
    asm volatile(
        "mma.sync.aligned.m16n8k16.row.col.f32.f16.f16.f32 "
        "{%0,%1,%2,%3}, {%4,%5,%6,%7}, {%8,%9}, {%0,%1,%2,%3};"
        : "+f"(c[0]), "+f"(c[1]), "+f"(c[2]), "+f"(c[3])
        : "r"(a[0]), "r"(a[1]), "r"(a[2]), "r"(a[3]), "r"(b[0]), "r"(b[1]));
}

// ---------------------------------------------------------------------------
// Kernel 2: split-fp16 distance GEMM with FUSED per-tile top-10 selection.
// d2 is never materialized: each 128x128 tile is staged in smem and reduced
// to 10 candidates per row (exact packed keys -> lossless for global top-10).
//   d2[i][j] = fl( fl(sq_i - 2*dot) + sq_j )   (pass 1, rows i)
//   d2[j][i] = fl( fl(sq_j - 2*dot) + sq_i )   (pass 2, rows j, off-diag only)
// ---------------------------------------------------------------------------
#define KCHUNK      64
#define NCHUNK      (DIMK / KCHUNK)         // 8
#define MAT_BYTES   (128 * 128)             // 128 rows x 128 B/row
#define STAGE_BYTES (4 * MAT_BYTES)         // 64 KB
#define DSMEM_BYTES (2 * STAGE_BYTES)       // 128 KB

__device__ __forceinline__ uint32_t sw128(uint32_t row, uint32_t cb) {
    return row * 128u + (cb ^ ((row & 7u) << 4));
}

__device__ __forceinline__ void issue_loads(uint32_t dsm_base, int chunk,
                                            int tid, int i0, int j0) {
    uint32_t bufbase = dsm_base + (chunk & 1) * STAGE_BYTES;
    int kof = chunk * KCHUNK;
#pragma unroll
    for (int i = 0; i < 16; i++) {
        int o   = tid + i * 256;        // 0..4095 16B-segments
        int mat = o >> 10;              // 0:Ahi 1:Alo 2:Bhi 3:Blo
        int r   = (o >> 3) & 127;
        int seg = o & 7;
        int rowbase = (mat >= 2) ? j0 : i0;
        const __half* base = (mat & 1) ? g_xlo : g_xhi;
        const __half* src = base + (size_t)(rowbase + r) * DIMK + kof + seg * 8;
        uint32_t dst = bufbase + mat * MAT_BYTES + sw128((uint32_t)r, (uint32_t)(seg * 16));
        asm volatile("cp.async.cg.shared.global [%0], [%1], 16;"
                     :: "r"(dst), "l"(src));
    }
    asm volatile("cp.async.commit_group;" ::: "memory");
}

__device__ __forceinline__ unsigned long long umin64(unsigned long long a,
                                                     unsigned long long b) {
    return a < b ? a : b;
}

// Per-warp scan: 16 rows of the staged tile -> 10 candidates each.
// lane q-th value: stage[row][lane + 32q], col = colbase + lane + 32q.
__device__ __forceinline__ void scan_tile(float (*stage)[132], int warp, int lane,
                                          int rowbase, int colbase, int tileslot) {
    for (int rr = 0; rr < 16; rr++) {
        int row = warp * 16 + rr;
        unsigned long long k[4];
#pragma unroll
        for (int q = 0; q < 4; q++) {
            float d = stage[row][lane + 32 * q];
            k[q] = ((unsigned long long)__float_as_uint(d) << 32)
                 | (unsigned)(colbase + lane + 32 * q);
        }
        // sort 4 ascending (network)
        unsigned long long t;
        if (k[0] > k[1]) { t = k[0]; k[0] = k[1]; k[1] = t; }
        if (k[2] > k[3]) { t = k[2]; k[2] = k[3]; k[3] = t; }
        if (k[0] > k[2]) { t = k[0]; k[0] = k[2]; k[2] = t; }
        if (k[1] > k[3]) { t = k[1]; k[1] = k[3]; k[3] = t; }
        if (k[1] > k[2]) { t = k[1]; k[1] = k[2]; k[2] = t; }

        unsigned long long mywin = 0;
#pragma unroll
        for (int r = 0; r < KNN; r++) {
            unsigned long long m = k[0];
#pragma unroll
            for (int o = 16; o; o >>= 1)
                m = umin64(m, __shfl_xor_sync(0xFFFFFFFFu, m, o));
            if (k[0] == m) {
                k[0] = k[1]; k[1] = k[2]; k[2] = k[3];
                k[3] = 0xFFFFFFFFFFFFFFFFull;
            }
            if (lane == r) mywin = m;
        }
        if (lane < KNN)
            g_cand[((size_t)(rowbase + row) * NTILE + tileslot) * KNN + lane] = mywin;
    }
}

__global__ void __launch_bounds__(256, 1) dist_mma_kernel() {
    // 1D triangular grid: bid -> (ib, jb), jb >= ib
    int bid = blockIdx.x;
    int ib = 0, base = 0;
    while (base + (NTILE - ib) <= bid) { base += NTILE - ib; ++ib; }
    int jb = ib + (bid - base);

    extern __shared__ __align__(1024) unsigned char dsm[];
    __shared__ float s_sqj[128];

    const int i0 = ib * 128;
    const int j0 = jb * 128;
    const int tid  = threadIdx.x;
    const int lane = tid & 31;
    const int warp = tid >> 5;
    const int wm = warp >> 2;       // 0..1 -> row offset wm*64
    const int wn = warp & 3;        // 0..3 -> col offset wn*32

    const uint32_t dsm_base = (uint32_t)__cvta_generic_to_shared(dsm);

    if (tid < 128) s_sqj[tid] = g_sq[j0 + tid];

    float acc[4][4][4];
#pragma unroll
    for (int a = 0; a < 4; a++)
#pragma unroll
        for (int b = 0; b < 4; b++)
#pragma unroll
            for (int c = 0; c < 4; c++) acc[a][b][c] = 0.0f;

    const uint32_t ar = (uint32_t)(wm * 64 + (lane & 15));   // + mt*16
    const uint32_t acb = (uint32_t)((lane >> 4) * 16);       // + ks*32
    const uint32_t br = (uint32_t)(wn * 32 + (lane & 7));    // + nt*8
    const uint32_t bcb = (uint32_t)(((lane >> 3) & 1) * 16); // + ks*32

    issue_loads(dsm_base, 0, tid, i0, j0);
    issue_loads(dsm_base, 1, tid, i0, j0);

    for (int c = 0; c < NCHUNK; c++) {
        if (c < NCHUNK - 1) asm volatile("cp.async.wait_group 1;" ::: "memory");
        else                asm volatile("cp.async.wait_group 0;" ::: "memory");
        __syncthreads();

        uint32_t stA = dsm_base + (c & 1) * STAGE_BYTES;
        uint32_t stB = stA + 2 * MAT_BYTES;

#pragma unroll
        for (int ks = 0; ks < 4; ks++) {
            uint32_t Ah[4][4], Al[4][4], Bh[4][2], Bl[4][2];
            const uint32_t acol = (uint32_t)(ks * 32) + acb;
            const uint32_t bcol = (uint32_t)(ks * 32) + bcb;
#pragma unroll
            for (int mt = 0; mt < 4; mt++) {
                uint32_t off = sw128(ar + mt * 16, acol);
                ldsm4_addr(Ah[mt][0], Ah[mt][1], Ah[mt][2], Ah[mt][3], stA + off);
                ldsm4_addr(Al[mt][0], Al[mt][1], Al[mt][2], Al[mt][3],
                           stA + MAT_BYTES + off);
            }
#pragma unroll
            for (int nt = 0; nt < 4; nt++) {
                uint32_t off = sw128(br + nt * 8, bcol);
                ldsm2_addr(Bh[nt][0], Bh[nt][1], stB + off);
                ldsm2_addr(Bl[nt][0], Bl[nt][1], stB + MAT_BYTES + off);
            }
#pragma unroll
            for (int mt = 0; mt < 4; mt++)
#pragma unroll
                for (int nt = 0; nt < 4; nt++) {
                    mma16816(acc[mt][nt], Ah[mt], Bh[nt]);   // hi*hi
                    mma16816(acc[mt][nt], Ah[mt], Bl[nt]);   // hi*lo
                    mma16816(acc[mt][nt], Al[mt], Bh[nt]);   // lo*hi
                }
        }

        __syncthreads();
        if (c + 2 < NCHUNK) issue_loads(dsm_base, c + 2, tid, i0, j0);
    }

    // Fragment -> (row, col) mapping
    const int r_in = lane >> 2;          // 0..7
    const int c_in = (lane & 3) * 2;     // 0,2,4,6

    float sqi[8], sqj[8];
#pragma unroll
    for (int mt = 0; mt < 4; mt++) {
        sqi[mt * 2 + 0] = g_sq[i0 + wm * 64 + mt * 16 + r_in];
        sqi[mt * 2 + 1] = g_sq[i0 + wm * 64 + mt * 16 + r_in + 8];
    }
#pragma unroll
    for (int nt = 0; nt < 4; nt++) {
        sqj[nt * 2 + 0] = s_sqj[wn * 32 + nt * 8 + c_in];
        sqj[nt * 2 + 1] = s_sqj[wn * 32 + nt * 8 + c_in + 1];
    }

    float (*stage)[132] = (float(*)[132])dsm;

    // ---- Pass 1: normal orientation, rows i. d2 = (sq_i - 2*dot) + sq_j ----
    __syncthreads();   // k-loop fully done before smem reuse
#pragma unroll
    for (int mt = 0; mt < 4; mt++) {
#pragma unroll
        for (int nt = 0; nt < 4; nt++) {
            int r  = wm * 64 + mt * 16 + r_in;
            int cc = wn * 32 + nt * 8 + c_in;
            stage[r    ][cc    ] = fmaxf((sqi[mt*2]   - 2.0f * acc[mt][nt][0]) + sqj[nt*2],   0.0f);
            stage[r    ][cc + 1] = fmaxf((sqi[mt*2]   - 2.0f * acc[mt][nt][1]) + sqj[nt*2+1], 0.0f);
            stage[r + 8][cc    ] = fmaxf((sqi[mt*2+1] - 2.0f * acc[mt][nt][2]) + sqj[nt*2],   0.0f);
            stage[r + 8][cc + 1] = fmaxf((sqi[mt*2+1] - 2.0f * acc[mt][nt][3]) + sqj[nt*2+1], 0.0f);
        }
    }
    __syncthreads();
    scan_tile(stage, warp, lane, i0, j0, jb);

    // ---- Pass 2: mirror orientation, rows j (off-diagonal CTAs only) ----
    if (ib != jb) {
        __syncthreads();
#pragma unroll
        for (int mt = 0; mt < 4; mt++) {
#pragma unroll
            for (int nt = 0; nt < 4; nt++) {
                int r  = wm * 64 + mt * 16 + r_in;
                int cc = wn * 32 + nt * 8 + c_in;
                stage[cc    ][r    ] = fmaxf((sqj[nt*2]   - 2.0f * acc[mt][nt][0]) + sqi[mt*2],   0.0f);
                stage[cc + 1][r    ] = fmaxf((sqj[nt*2+1] - 2.0f * acc[mt][nt][1]) + sqi[mt*2],   0.0f);
                stage[cc    ][r + 8] = fmaxf((sqj[nt*2]   - 2.0f * acc[mt][nt][2]) + sqi[mt*2+1], 0.0f);
                stage[cc + 1][r + 8] = fmaxf((sqj[nt*2+1] - 2.0f * acc[mt][nt][3]) + sqi[mt*2+1], 0.0f);
            }
        }
        __syncthreads();
        scan_tile(stage, warp, lane, j0, i0, ib);
    }
}

// ---------------------------------------------------------------------------
// Kernel 3: merge 64x10 candidates per row -> global top-10, then smoothing.
// One block (128 threads) per row; each thread takes 5 candidates.
// ---------------------------------------------------------------------------
__global__ void __launch_bounds__(128) merge_smooth_kernel(const float* __restrict__ x,
                                                           float* __restrict__ out) {
    const int row = blockIdx.x;
    const int tid = threadIdx.x;
    const unsigned long long* crow = g_cand + (size_t)row * NTILE * KNN;

    unsigned long long keys[KNN];
#pragma unroll
    for (int i = 0; i < KNN; i++) keys[i] = 0xFFFFFFFFFFFFFFFFull;

#pragma unroll
    for (int q = 0; q < 5; q++) {
        unsigned long long key = crow[tid + q * 128];
        if (key < keys[KNN - 1]) {
            keys[KNN - 1] = key;
#pragma unroll
            for (int p = KNN - 1; p > 0; p--) {
                if (keys[p] < keys[p - 1]) {
                    unsigned long long tmp = keys[p];
                    keys[p] = keys[p - 1];
                    keys[p - 1] = tmp;
                }
            }
        }
    }

    __shared__ unsigned long long sdata[128];
    __shared__ int sel[KNN];

    for (int r = 0; r < KNN; r++) {
        sdata[tid] = keys[0];
        __syncthreads();
#pragma unroll
        for (int s = 64; s > 0; s >>= 1) {
            if (tid < s) {
                unsigned long long o = sdata[tid + s];
                if (o < sdata[tid]) sdata[tid] = o;
            }
            __syncthreads();
        }
        unsigned long long win = sdata[0];
        if (tid == 0) sel[r] = (int)(win & 0xFFFFFFFFull);
        if (keys[0] == win) {
#pragma unroll
            for (int p = 0; p < KNN - 1; p++) keys[p] = keys[p + 1];
            keys[KNN - 1] = 0xFFFFFFFFFFFFFFFFull;
        }
        __syncthreads();
    }

    float4 acc = make_float4(0.0f, 0.0f, 0.0f, 0.0f);
#pragma unroll
    for (int r = 0; r < KNN; r++) {
        float4 v = ((const float4*)(x + (size_t)sel[r] * DIMK))[tid];
        acc.x += v.x; acc.y += v.y; acc.z += v.z; acc.w += v.w;
    }
    float4 xi = ((const float4*)(x + (size_t)row * DIMK))[tid];
    const float w = 0.5f / (float)KNN;
    float4 o;
    o.x = 0.5f * xi.x + w * acc.x;
    o.y = 0.5f * xi.y + w * acc.y;
    o.z = 0.5f * xi.z + w * acc.z;
    o.w = 0.5f * xi.w + w * acc.w;
    ((float4*)(out + (size_t)row * DIMK))[tid] = o;
}

// ---------------------------------------------------------------------------
extern "C" void kernel_launch(void* const* d_in, const int* in_sizes, int n_in,
                              void* d_out, int out_size) {
    const float* x = (const float*)d_in[0];
    float* out = (float*)d_out;

    cudaFuncSetAttribute(dist_mma_kernel,
                         cudaFuncAttributeMaxDynamicSharedMemorySize, DSMEM_BYTES);

    prep_kernel<<<N_PTS / 8, 256>>>(x);
    dist_mma_kernel<<<NTILE * (NTILE + 1) / 2, 256, DSMEM_BYTES>>>();
    merge_smooth_kernel<<<N_PTS, 128>>>(x, out);
}

// round 7
// speedup vs baseline: 1.3366x; 1.3366x over previous
#include <cuda_runtime.h>
#include <cuda_fp16.h>
#include <cstdint>

#define N_PTS 8192
#define DIMK  512
#define KNN   10
#define NTILE (N_PTS / 128)      // 64 column tiles per row
#define CPT   20                 // candidates per (row, tile): 2 halves x 10

// Static device scratch (no runtime allocation allowed)
__device__ float  g_sq[N_PTS];
__device__ __half g_xhi[(size_t)N_PTS * DIMK];     // 8 MB
__device__ __half g_xlo[(size_t)N_PTS * DIMK];     // 8 MB
// Per-(row, tile) candidates, key = (d2_bits<<32)|col : 84 MB
__device__ unsigned long long g_cand[(size_t)N_PTS * NTILE * CPT];

// ---------------------------------------------------------------------------
// Kernel 1: fused prep — fp16 2-split of x AND fp64 squared norms.
// ---------------------------------------------------------------------------
__global__ void __launch_bounds__(256) prep_kernel(const float* __restrict__ x) {
    int row  = blockIdx.x * 8 + (threadIdx.x >> 5);
    int lane = threadIdx.x & 31;
    const float4* xr = (const float4*)(x + (size_t)row * DIMK);
    double s = 0.0;
#pragma unroll
    for (int t = 0; t < 4; t++) {
        int e = lane + t * 32;
        float4 v = xr[e];
        __half h[4], l[4];
        h[0] = __float2half_rn(v.x);  l[0] = __float2half_rn(v.x - __half2float(h[0]));
        h[1] = __float2half_rn(v.y);  l[1] = __float2half_rn(v.y - __half2float(h[1]));
        h[2] = __float2half_rn(v.z);  l[2] = __float2half_rn(v.z - __half2float(h[2]));
        h[3] = __float2half_rn(v.w);  l[3] = __float2half_rn(v.w - __half2float(h[3]));
        *(uint2*)&g_xhi[(size_t)row * DIMK + e * 4] = *(uint2*)h;
        *(uint2*)&g_xlo[(size_t)row * DIMK + e * 4] = *(uint2*)l;
        s += (double)v.x * v.x + (double)v.y * v.y
           + (double)v.z * v.z + (double)v.w * v.w;
    }
#pragma unroll
    for (int o = 16; o; o >>= 1)
        s += __shfl_xor_sync(0xFFFFFFFFu, s, o);
    if (lane == 0) g_sq[row] = (float)s;
}

// ---------------------------------------------------------------------------
// HMMA helpers
// ---------------------------------------------------------------------------
__device__ __forceinline__ void ldsm4_addr(uint32_t& r0, uint32_t& r1,
                                           uint32_t& r2, uint32_t& r3, uint32_t a) {
    asm volatile("ldmatrix.sync.aligned.m8n8.x4.shared.b16 {%0,%1,%2,%3}, [%4];"
                 : "=r"(r0), "=r"(r1), "=r"(r2), "=r"(r3) : "r"(a));
}
__device__ __forceinline__ void ldsm2_addr(uint32_t& r0, uint32_t& r1, uint32_t a) {
    asm volatile("ldmatrix.sync.aligned.m8n8.x2.shared.b16 {%0,%1}, [%2];"
                 : "=r"(r0), "=r"(r1) : "r"(a));
}
__device__ __forceinline__ void mma16816(float c[4], const uint32_t a[4],
                                         const uint32_t b[2]) {
    asm volatile(
        "mma.sync.aligned.m16n8k16.row.col.f32.f16.f16.f32 "
        "{%0,%1,%2,%3}, {%4,%5,%6,%7}, {%8,%9}, {%0,%1,%2,%3};"
        : "+f"(c[0]), "+f"(c[1]), "+f"(c[2]), "+f"(c[3])
        : "r"(a[0]), "r"(a[1]), "r"(a[2]), "r"(a[3]), "r"(b[0]), "r"(b[1]));
}

// ---------------------------------------------------------------------------
// Kernel 2: split-fp16 distance GEMM + fused per-tile candidate selection.
// The 128x128 dot tile is staged ONCE (raw dot); both orientations' exact
// rounding formulas are applied during the scans:
//   pass1 rows i: d2 = fl( fl(sq_i - 2*dot) + sq_j )
//   pass2 rows j: d2 = fl( fl(sq_j - 2*dot) + sq_i )   (off-diagonal CTAs)
// Selection: per-thread sorted-insertion over 64 values (no shfl chains).
// ---------------------------------------------------------------------------
#define KCHUNK      64
#define NCHUNK      (DIMK / KCHUNK)         // 8
#define MAT_BYTES   (128 * 128)
#define STAGE_BYTES (4 * MAT_BYTES)         // 64 KB
#define DSMEM_BYTES (2 * STAGE_BYTES)       // 128 KB
#define SPITCH      133                     // stage row pitch (floats)

__device__ __forceinline__ uint32_t sw128(uint32_t row, uint32_t cb) {
    return row * 128u + (cb ^ ((row & 7u) << 4));
}

__device__ __forceinline__ void issue_loads(uint32_t dsm_base, int chunk,
                                            int tid, int i0, int j0) {
    uint32_t bufbase = dsm_base + (chunk & 1) * STAGE_BYTES;
    int kof = chunk * KCHUNK;
#pragma unroll
    for (int i = 0; i < 16; i++) {
        int o   = tid + i * 256;
        int mat = o >> 10;              // 0:Ahi 1:Alo 2:Bhi 3:Blo
        int r   = (o >> 3) & 127;
        int seg = o & 7;
        int rowbase = (mat >= 2) ? j0 : i0;
        const __half* base = (mat & 1) ? g_xlo : g_xhi;
        const __half* src = base + (size_t)(rowbase + r) * DIMK + kof + seg * 8;
        uint32_t dst = bufbase + mat * MAT_BYTES + sw128((uint32_t)r, (uint32_t)(seg * 16));
        asm volatile("cp.async.cg.shared.global [%0], [%1], 16;"
                     :: "r"(dst), "l"(src));
    }
    asm volatile("cp.async.commit_group;" ::: "memory");
}

// Sorted-insertion of key into ascending keys[KNN]
__device__ __forceinline__ void ins10(unsigned long long keys[KNN],
                                      unsigned long long key) {
    if (key < keys[KNN - 1]) {
        keys[KNN - 1] = key;
#pragma unroll
        for (int p = KNN - 1; p > 0; p--) {
            if (keys[p] < keys[p - 1]) {
                unsigned long long t = keys[p];
                keys[p] = keys[p - 1];
                keys[p - 1] = t;
            }
        }
    }
}

__global__ void __launch_bounds__(256, 1) dist_mma_kernel() {
    // 1D triangular grid: bid -> (ib, jb), jb >= ib
    int bid = blockIdx.x;
    int ib = 0, base = 0;
    while (base + (NTILE - ib) <= bid) { base += NTILE - ib; ++ib; }
    int jb = ib + (bid - base);

    extern __shared__ __align__(1024) unsigned char dsm[];
    __shared__ float s_sqi[128];
    __shared__ float s_sqj[128];

    const int i0 = ib * 128;
    const int j0 = jb * 128;
    const int tid  = threadIdx.x;
    const int lane = tid & 31;
    const int warp = tid >> 5;
    const int wm = warp >> 2;
    const int wn = warp & 3;

    const uint32_t dsm_base = (uint32_t)__cvta_generic_to_shared(dsm);

    if (tid < 128) {
        s_sqi[tid] = g_sq[i0 + tid];
        s_sqj[tid] = g_sq[j0 + tid];
    }

    float acc[4][4][4];
#pragma unroll
    for (int a = 0; a < 4; a++)
#pragma unroll
        for (int b = 0; b < 4; b++)
#pragma unroll
            for (int c = 0; c < 4; c++) acc[a][b][c] = 0.0f;

    const uint32_t ar = (uint32_t)(wm * 64 + (lane & 15));
    const uint32_t acb = (uint32_t)((lane >> 4) * 16);
    const uint32_t br = (uint32_t)(wn * 32 + (lane & 7));
    const uint32_t bcb = (uint32_t)(((lane >> 3) & 1) * 16);

    issue_loads(dsm_base, 0, tid, i0, j0);
    issue_loads(dsm_base, 1, tid, i0, j0);

    for (int c = 0; c < NCHUNK; c++) {
        if (c < NCHUNK - 1) asm volatile("cp.async.wait_group 1;" ::: "memory");
        else                asm volatile("cp.async.wait_group 0;" ::: "memory");
        __syncthreads();

        uint32_t stA = dsm_base + (c & 1) * STAGE_BYTES;
        uint32_t stB = stA + 2 * MAT_BYTES;

#pragma unroll
        for (int ks = 0; ks < 4; ks++) {
            uint32_t Ah[4][4], Al[4][4], Bh[4][2], Bl[4][2];
            const uint32_t acol = (uint32_t)(ks * 32) + acb;
            const uint32_t bcol = (uint32_t)(ks * 32) + bcb;
#pragma unroll
            for (int mt = 0; mt < 4; mt++) {
                uint32_t off = sw128(ar + mt * 16, acol);
                ldsm4_addr(Ah[mt][0], Ah[mt][1], Ah[mt][2], Ah[mt][3], stA + off);
                ldsm4_addr(Al[mt][0], Al[mt][1], Al[mt][2], Al[mt][3],
                           stA + MAT_BYTES + off);
            }
#pragma unroll
            for (int nt = 0; nt < 4; nt++) {
                uint32_t off = sw128(br + nt * 8, bcol);
                ldsm2_addr(Bh[nt][0], Bh[nt][1], stB + off);
                ldsm2_addr(Bl[nt][0], Bl[nt][1], stB + MAT_BYTES + off);
            }
#pragma unroll
            for (int mt = 0; mt < 4; mt++)
#pragma unroll
                for (int nt = 0; nt < 4; nt++) {
                    mma16816(acc[mt][nt], Ah[mt], Bh[nt]);   // hi*hi
                    mma16816(acc[mt][nt], Ah[mt], Bl[nt]);   // hi*lo
                    mma16816(acc[mt][nt], Al[mt], Bh[nt]);   // lo*hi
                }
        }

        __syncthreads();
        if (c + 2 < NCHUNK) issue_loads(dsm_base, c + 2, tid, i0, j0);
    }
    // trailing __syncthreads of the loop guarantees all smem reads done

    // Stage raw dot values (single orientation-agnostic copy)
    float (*stage)[SPITCH] = (float(*)[SPITCH])dsm;
    const int r_in = lane >> 2;
    const int c_in = (lane & 3) * 2;
#pragma unroll
    for (int mt = 0; mt < 4; mt++) {
#pragma unroll
        for (int nt = 0; nt < 4; nt++) {
            int r  = wm * 64 + mt * 16 + r_in;
            int cc = wn * 32 + nt * 8 + c_in;
            stage[r    ][cc    ] = acc[mt][nt][0];
            stage[r    ][cc + 1] = acc[mt][nt][1];
            stage[r + 8][cc    ] = acc[mt][nt][2];
            stage[r + 8][cc + 1] = acc[mt][nt][3];
        }
    }
    __syncthreads();

    const int rl   = tid >> 1;        // 0..127 (row for pass1 / col for pass2)
    const int half = tid & 1;         // which 64-column half
    const int hb   = half * 64;

    // ---- Pass 1: rows i. d2 = (sq_i - 2*dot) + sq_j ----
    {
        unsigned long long keys[KNN];
#pragma unroll
        for (int q = 0; q < KNN; q++) keys[q] = 0xFFFFFFFFFFFFFFFFull;
        const float sqi_r = s_sqi[rl];
        for (int v = 0; v < 64; v++) {
            float d = fmaxf((sqi_r - 2.0f * stage[rl][hb + v]) + s_sqj[hb + v], 0.0f);
            ins10(keys, ((unsigned long long)__float_as_uint(d) << 32)
                        | (unsigned)(j0 + hb + v));
        }
        unsigned long long* dst =
            &g_cand[((size_t)(i0 + rl) * NTILE + jb) * CPT + half * KNN];
#pragma unroll
        for (int q = 0; q < KNN; q++) dst[q] = keys[q];
    }

    // ---- Pass 2: rows j (off-diagonal CTAs). d2 = (sq_j - 2*dot) + sq_i ----
    if (ib != jb) {
        unsigned long long keys[KNN];
#pragma unroll
        for (int q = 0; q < KNN; q++) keys[q] = 0xFFFFFFFFFFFFFFFFull;
        const float sqj_c = s_sqj[rl];
        for (int v = 0; v < 64; v++) {
            int il = hb + v;
            float d = fmaxf((sqj_c - 2.0f * stage[il][rl]) + s_sqi[il], 0.0f);
            ins10(keys, ((unsigned long long)__float_as_uint(d) << 32)
                        | (unsigned)(i0 + il));
        }
        unsigned long long* dst =
            &g_cand[((size_t)(j0 + rl) * NTILE + ib) * CPT + half * KNN];
#pragma unroll
        for (int q = 0; q < KNN; q++) dst[q] = keys[q];
    }
}

// ---------------------------------------------------------------------------
// Kernel 3: merge 64x20 candidates per row -> global top-10, then smoothing.
// One block (128 threads) per row; each thread takes 10 candidates.
// ---------------------------------------------------------------------------
__global__ void __launch_bounds__(128) merge_smooth_kernel(const float* __restrict__ x,
                                                           float* __restrict__ out) {
    const int row = blockIdx.x;
    const int tid = threadIdx.x;
    const unsigned long long* crow = g_cand + (size_t)row * NTILE * CPT;

    unsigned long long keys[KNN];
#pragma unroll
    for (int i = 0; i < KNN; i++) keys[i] = 0xFFFFFFFFFFFFFFFFull;

#pragma unroll
    for (int q = 0; q < 10; q++) {
        unsigned long long key = crow[tid + q * 128];
        if (key < keys[KNN - 1]) {
            keys[KNN - 1] = key;
#pragma unroll
            for (int p = KNN - 1; p > 0; p--) {
                if (keys[p] < keys[p - 1]) {
                    unsigned long long tmp = keys[p];
                    keys[p] = keys[p - 1];
                    keys[p - 1] = tmp;
                }
            }
        }
    }

    __shared__ unsigned long long sdata[128];
    __shared__ int sel[KNN];

    for (int r = 0; r < KNN; r++) {
        sdata[tid] = keys[0];
        __syncthreads();
#pragma unroll
        for (int s = 64; s > 0; s >>= 1) {
            if (tid < s) {
                unsigned long long o = sdata[tid + s];
                if (o < sdata[tid]) sdata[tid] = o;
            }
            __syncthreads();
        }
        unsigned long long win = sdata[0];
        if (tid == 0) sel[r] = (int)(win & 0xFFFFFFFFull);
        if (keys[0] == win) {
#pragma unroll
            for (int p = 0; p < KNN - 1; p++) keys[p] = keys[p + 1];
            keys[KNN - 1] = 0xFFFFFFFFFFFFFFFFull;
        }
        __syncthreads();
    }

    float4 acc = make_float4(0.0f, 0.0f, 0.0f, 0.0f);
#pragma unroll
    for (int r = 0; r < KNN; r++) {
        float4 v = ((const float4*)(x + (size_t)sel[r] * DIMK))[tid];
        acc.x += v.x; acc.y += v.y; acc.z += v.z; acc.w += v.w;
    }
    float4 xi = ((const float4*)(x + (size_t)row * DIMK))[tid];
    const float w = 0.5f / (float)KNN;
    float4 o;
    o.x = 0.5f * xi.x + w * acc.x;
    o.y = 0.5f * xi.y + w * acc.y;
    o.z = 0.5f * xi.z + w * acc.z;
    o.w = 0.5f * xi.w + w * acc.w;
    ((float4*)(out + (size_t)row * DIMK))[tid] = o;
}

// ---------------------------------------------------------------------------
extern "C" void kernel_launch(void* const* d_in, const int* in_sizes, int n_in,
                              void* d_out, int out_size) {
    const float* x = (const float*)d_in[0];
    float* out = (float*)d_out;

    cudaFuncSetAttribute(dist_mma_kernel,
                         cudaFuncAttributeMaxDynamicSharedMemorySize, DSMEM_BYTES);

    prep_kernel<<<N_PTS / 8, 256>>>(x);
    dist_mma_kernel<<<NTILE * (NTILE + 1) / 2, 256, DSMEM_BYTES>>>();
    merge_smooth_kernel<<<N_PTS, 128>>>(x, out);
}

// round 9
// speedup vs baseline: 1.6417x; 1.2283x over previous
#include <cuda_runtime.h>
#include <cuda_fp16.h>
#include <cstdint>

#define N_PTS 8192
#define DIMK  512
#define KNN   10
#define NTILE (N_PTS / 128)      // 64 column tiles per row
#define CPT   20                 // candidates per (row, tile): 2 halves x 10

// Static device scratch (no runtime allocation allowed)
__device__ float  g_sq[N_PTS];
__device__ __half g_xhi[(size_t)N_PTS * DIMK];     // 8 MB
__device__ __half g_xlo[(size_t)N_PTS * DIMK];     // 8 MB
// Per-(row, tile) candidates, key = (d2_bits<<32)|col : 84 MB
__device__ unsigned long long g_cand[(size_t)N_PTS * NTILE * CPT];

// ---------------------------------------------------------------------------
// Kernel 1: fused prep — fp16 2-split of x AND fp64 squared norms.
// ---------------------------------------------------------------------------
__global__ void __launch_bounds__(256) prep_kernel(const float* __restrict__ x) {
    int row  = blockIdx.x * 8 + (threadIdx.x >> 5);
    int lane = threadIdx.x & 31;
    const float4* xr = (const float4*)(x + (size_t)row * DIMK);
    double s = 0.0;
#pragma unroll
    for (int t = 0; t < 4; t++) {
        int e = lane + t * 32;
        float4 v = xr[e];
        __half h[4], l[4];
        h[0] = __float2half_rn(v.x);  l[0] = __float2half_rn(v.x - __half2float(h[0]));
        h[1] = __float2half_rn(v.y);  l[1] = __float2half_rn(v.y - __half2float(h[1]));
        h[2] = __float2half_rn(v.z);  l[2] = __float2half_rn(v.z - __half2float(h[2]));
        h[3] = __float2half_rn(v.w);  l[3] = __float2half_rn(v.w - __half2float(h[3]));
        *(uint2*)&g_xhi[(size_t)row * DIMK + e * 4] = *(uint2*)h;
        *(uint2*)&g_xlo[(size_t)row * DIMK + e * 4] = *(uint2*)l;
        s += (double)v.x * v.x + (double)v.y * v.y
           + (double)v.z * v.z + (double)v.w * v.w;
    }
#pragma unroll
    for (int o = 16; o; o >>= 1)
        s += __shfl_xor_sync(0xFFFFFFFFu, s, o);
    if (lane == 0) g_sq[row] = (float)s;
}

// ---------------------------------------------------------------------------
// HMMA helpers
// ---------------------------------------------------------------------------
__device__ __forceinline__ void ldsm4_addr(uint32_t& r0, uint32_t& r1,
                                           uint32_t& r2, uint32_t& r3, uint32_t a) {
    asm volatile("ldmatrix.sync.aligned.m8n8.x4.shared.b16 {%0,%1,%2,%3}, [%4];"
                 : "=r"(r0), "=r"(r1), "=r"(r2), "=r"(r3) : "r"(a));
}
__device__ __forceinline__ void ldsm2_addr(uint32_t& r0, uint32_t& r1, uint32_t a) {
    asm volatile("ldmatrix.sync.aligned.m8n8.x2.shared.b16 {%0,%1}, [%2];"
                 : "=r"(r0), "=r"(r1) : "r"(a));
}
__device__ __forceinline__ void mma16816(float c[4], const uint32_t a[4],
                                         const uint32_t b[2]) {
    asm volatile(
        "mma.sync.aligned.m16n8k16.row.col.f32.f16.f16.f32 "
        "{%0,%1,%2,%3}, {%4,%5,%6,%7}, {%8,%9}, {%0,%1,%2,%3};"
        : "+f"(c[0]), "+f"(c[1]), "+f"(c[2]), "+f"(c[3])
        : "r"(a[0]), "r"(a[1]), "r"(a[2]), "r"(a[3]), "r"(b[0]), "r"(b[1]));
}

// ---------------------------------------------------------------------------
// Kernel 2: split-fp16 distance GEMM + fused per-tile candidate selection.
// BK=32, 2-stage cp.async pipeline (2 x 32 KB) so smem fits 2 CTAs/SM:
// selection of one CTA overlaps the other CTA's MMA bursts.
// Stage layout per matrix: 64 physical 128B rows; matrix row r lives at
// physical row (r&63), 64B half (r>>6); SW128 XOR applied to the full 128B
// row offset (bijective, loader/reader symmetric).
//   pass1 rows i: d2 = fl( fl(sq_i - 2*dot) + sq_j )
//   pass2 rows j: d2 = fl( fl(sq_j - 2*dot) + sq_i )   (off-diagonal CTAs)
// ---------------------------------------------------------------------------
#define KCHUNK      32
#define NCHUNK      (DIMK / KCHUNK)         // 16
#define MATB        8192                    // bytes per matrix per stage
#define STAGEB      (4 * MATB)              // 32 KB
#define SPITCH      133                     // selection stage pitch (floats)
#define DSMEM_BYTES 69632                   // max(2*32KB pipeline, 68.1KB stage)

__device__ __forceinline__ uint32_t swz(uint32_t r, uint32_t w) {
    return (r & 63u) * 128u + (w ^ ((r & 7u) << 4));
}

__device__ __forceinline__ void issue_loads(uint32_t dsm_base, int chunk,
                                            int tid, int i0, int j0) {
    uint32_t bufbase = dsm_base + (chunk & 1) * STAGEB;
    int kof = chunk * KCHUNK;
#pragma unroll
    for (int i = 0; i < 8; i++) {
        int o   = tid + i * 256;        // 0..2047 16B-segments
        int mat = o >> 9;               // 0:Ahi 1:Alo 2:Bhi 3:Blo
        int rem = o & 511;
        int r   = rem >> 2;             // 0..127
        int s   = rem & 3;              // 16B segment within 64B row
        int rowbase = (mat >= 2) ? j0 : i0;
        const __half* base = (mat & 1) ? g_xlo : g_xhi;
        const __half* src = base + (size_t)(rowbase + r) * DIMK + kof + s * 8;
        uint32_t w = (uint32_t)(((r >> 6) << 6) | (s * 16));
        uint32_t dst = bufbase + mat * MATB + swz((uint32_t)r, w);
        asm volatile("cp.async.cg.shared.global [%0], [%1], 16;"
                     :: "r"(dst), "l"(src));
    }
    asm volatile("cp.async.commit_group;" ::: "memory");
}

// Sorted-insertion of key into ascending keys[KNN]
__device__ __forceinline__ void ins10(unsigned long long keys[KNN],
                                      unsigned long long key) {
    if (key < keys[KNN - 1]) {
        keys[KNN - 1] = key;
#pragma unroll
        for (int p = KNN - 1; p > 0; p--) {
            if (keys[p] < keys[p - 1]) {
                unsigned long long t = keys[p];
                keys[p] = keys[p - 1];
                keys[p - 1] = t;
            }
        }
    }
}

__global__ void __launch_bounds__(256, 2) dist_mma_kernel() {
    // 1D triangular grid: bid -> (ib, jb), jb >= ib
    int bid = blockIdx.x;
    int ib = 0, base = 0;
    while (base + (NTILE - ib) <= bid) { base += NTILE - ib; ++ib; }
    int jb = ib + (bid - base);

    extern __shared__ __align__(1024) unsigned char dsm[];
    __shared__ float s_sqi[128];
    __shared__ float s_sqj[128];

    const int i0 = ib * 128;
    const int j0 = jb * 128;
    const int tid  = threadIdx.x;
    const int lane = tid & 31;
    const int warp = tid >> 5;
    const int wm = warp >> 2;
    const int wn = warp & 3;

    const uint32_t dsm_base = (uint32_t)__cvta_generic_to_shared(dsm);

    if (tid < 128) {
        s_sqi[tid] = g_sq[i0 + tid];
        s_sqj[tid] = g_sq[j0 + tid];
    }

    float acc[4][4][4];
#pragma unroll
    for (int a = 0; a < 4; a++)
#pragma unroll
        for (int b = 0; b < 4; b++)
#pragma unroll
            for (int c = 0; c < 4; c++) acc[a][b][c] = 0.0f;

    issue_loads(dsm_base, 0, tid, i0, j0);
    issue_loads(dsm_base, 1, tid, i0, j0);

    const uint32_t Arow = (uint32_t)(wm * 64 + (lane & 15));   // + mt*16
    const uint32_t Acb  = (uint32_t)((lane >> 4) * 16);        // + ks*32
    const uint32_t Brow = (uint32_t)(wn * 32 + (lane & 7));    // + nt*8
    const uint32_t Bcb  = (uint32_t)(((lane >> 3) & 1) * 16);  // + ks*32

    for (int c = 0; c < NCHUNK; c++) {
        if (c < NCHUNK - 1) asm volatile("cp.async.wait_group 1;" ::: "memory");
        else                asm volatile("cp.async.wait_group 0;" ::: "memory");
        __syncthreads();

        uint32_t st = dsm_base + (c & 1) * STAGEB;

#pragma unroll
        for (int ks = 0; ks < 2; ks++) {
            uint32_t Ah[4][4], Al[4][4], Bh[4][2], Bl[4][2];
            const uint32_t acb = (uint32_t)(ks * 32) + Acb;   // 0..63
            const uint32_t bcb = (uint32_t)(ks * 32) + Bcb;
#pragma unroll
            for (int mt = 0; mt < 4; mt++) {
                uint32_t R = Arow + mt * 16;
                uint32_t w = ((R >> 6) << 6) | acb;
                uint32_t off = swz(R, w);
                ldsm4_addr(Ah[mt][0], Ah[mt][1], Ah[mt][2], Ah[mt][3], st + off);
                ldsm4_addr(Al[mt][0], Al[mt][1], Al[mt][2], Al[mt][3],
                           st + MATB + off);
            }
#pragma unroll
            for (int nt = 0; nt < 4; nt++) {
                uint32_t R = Brow + nt * 8;
                uint32_t w = ((R >> 6) << 6) | bcb;
                uint32_t off = swz(R, w);
                ldsm2_addr(Bh[nt][0], Bh[nt][1], st + 2 * MATB + off);
                ldsm2_addr(Bl[nt][0], Bl[nt][1], st + 3 * MATB + off);
            }
#pragma unroll
            for (int mt = 0; mt < 4; mt++)
#pragma unroll
                for (int nt = 0; nt < 4; nt++) {
                    mma16816(acc[mt][nt], Ah[mt], Bh[nt]);   // hi*hi
                    mma16816(acc[mt][nt], Ah[mt], Bl[nt]);   // hi*lo
                    mma16816(acc[mt][nt], Al[mt], Bh[nt]);   // lo*hi
                }
        }

        __syncthreads();
        if (c + 2 < NCHUNK) issue_loads(dsm_base, c + 2, tid, i0, j0);
    }

    // Stage raw dot values (single orientation-agnostic copy)
    float (*stage)[SPITCH] = (float(*)[SPITCH])dsm;
    const int r_in = lane >> 2;
    const int c_in = (lane & 3) * 2;
#pragma unroll
    for (int mt = 0; mt < 4; mt++) {
#pragma unroll
        for (int nt = 0; nt < 4; nt++) {
            int r  = wm * 64 + mt * 16 + r_in;
            int cc = wn * 32 + nt * 8 + c_in;
            stage[r    ][cc    ] = acc[mt][nt][0];
            stage[r    ][cc + 1] = acc[mt][nt][1];
            stage[r + 8][cc    ] = acc[mt][nt][2];
            stage[r + 8][cc + 1] = acc[mt][nt][3];
        }
    }
    __syncthreads();

    const int rl   = tid >> 1;        // 0..127 (row for pass1 / col for pass2)
    const int half = tid & 1;         // which 64-column half
    const int hb   = half * 64;

    // ---- Pass 1: rows i. d2 = (sq_i - 2*dot) + sq_j ----
    {
        unsigned long long keys[KNN];
#pragma unroll
        for (int q = 0; q < KNN; q++) keys[q] = 0xFFFFFFFFFFFFFFFFull;
        const float sqi_r = s_sqi[rl];
        for (int v = 0; v < 64; v++) {
            float d = fmaxf((sqi_r - 2.0f * stage[rl][hb + v]) + s_sqj[hb + v], 0.0f);
            // Threshold prefilter in UNSIGNED BIT space (d >= 0 -> monotone;
            // sentinel 0xFFFFFFFF acts as +inf). <= keeps tie lower-index.
            uint32_t db = __float_as_uint(d);
            if (db <= (uint32_t)(keys[KNN - 1] >> 32)) {
                ins10(keys, ((unsigned long long)db << 32)
                            | (unsigned)(j0 + hb + v));
            }
        }
        unsigned long long* dst =
            &g_cand[((size_t)(i0 + rl) * NTILE + jb) * CPT + half * KNN];
#pragma unroll
        for (int q = 0; q < KNN; q++) dst[q] = keys[q];
    }

    // ---- Pass 2: rows j (off-diagonal CTAs). d2 = (sq_j - 2*dot) + sq_i ----
    if (ib != jb) {
        unsigned long long keys[KNN];
#pragma unroll
        for (int q = 0; q < KNN; q++) keys[q] = 0xFFFFFFFFFFFFFFFFull;
        const float sqj_c = s_sqj[rl];
        for (int v = 0; v < 64; v++) {
            int il = hb + v;
            float d = fmaxf((sqj_c - 2.0f * stage[il][rl]) + s_sqi[il], 0.0f);
            uint32_t db = __float_as_uint(d);
            if (db <= (uint32_t)(keys[KNN - 1] >> 32)) {
                ins10(keys, ((unsigned long long)db << 32)
                            | (unsigned)(i0 + il));
            }
        }
        unsigned long long* dst =
            &g_cand[((size_t)(j0 + rl) * NTILE + ib) * CPT + half * KNN];
#pragma unroll
        for (int q = 0; q < KNN; q++) dst[q] = keys[q];
    }
}

// ---------------------------------------------------------------------------
// Kernel 3: merge 64x20 candidates per row -> global top-10, then smoothing.
// ---------------------------------------------------------------------------
__global__ void __launch_bounds__(128) merge_smooth_kernel(const float* __restrict__ x,
                                                           float* __restrict__ out) {
    const int row = blockIdx.x;
    const int tid = threadIdx.x;
    const unsigned long long* crow = g_cand + (size_t)row * NTILE * CPT;

    unsigned long long keys[KNN];
#pragma unroll
    for (int i = 0; i < KNN; i++) keys[i] = 0xFFFFFFFFFFFFFFFFull;

#pragma unroll
    for (int q = 0; q < 10; q++) {
        unsigned long long key = crow[tid + q * 128];
        if (key < keys[KNN - 1]) {
            keys[KNN - 1] = key;
#pragma unroll
            for (int p = KNN - 1; p > 0; p--) {
                if (keys[p] < keys[p - 1]) {
                    unsigned long long tmp = keys[p];
                    keys[p] = keys[p - 1];
                    keys[p - 1] = tmp;
                }
            }
        }
    }

    __shared__ unsigned long long sdata[128];
    __shared__ int sel[KNN];

    for (int r = 0; r < KNN; r++) {
        sdata[tid] = keys[0];
        __syncthreads();
#pragma unroll
        for (int s = 64; s > 0; s >>= 1) {
            if (tid < s) {
                unsigned long long o = sdata[tid + s];
                if (o < sdata[tid]) sdata[tid] = o;
            }
            __syncthreads();
        }
        unsigned long long win = sdata[0];
        if (tid == 0) sel[r] = (int)(win & 0xFFFFFFFFull);
        if (keys[0] == win) {
#pragma unroll
            for (int p = 0; p < KNN - 1; p++) keys[p] = keys[p + 1];
            keys[KNN - 1] = 0xFFFFFFFFFFFFFFFFull;
        }
        __syncthreads();
    }

    float4 acc = make_float4(0.0f, 0.0f, 0.0f, 0.0f);
#pragma unroll
    for (int r = 0; r < KNN; r++) {
        float4 v = ((const float4*)(x + (size_t)sel[r] * DIMK))[tid];
        acc.x += v.x; acc.y += v.y; acc.z += v.z; acc.w += v.w;
    }
    float4 xi = ((const float4*)(x + (size_t)row * DIMK))[tid];
    const float w = 0.5f / (float)KNN;
    float4 o;
    o.x = 0.5f * xi.x + w * acc.x;
    o.y = 0.5f * xi.y + w * acc.y;
    o.z = 0.5f * xi.z + w * acc.z;
    o.w = 0.5f * xi.w + w * acc.w;
    ((float4*)(out + (size_t)row * DIMK))[tid] = o;
}

// ---------------------------------------------------------------------------
extern "C" void kernel_launch(void* const* d_in, const int* in_sizes, int n_in,
                              void* d_out, int out_size) {
    const float* x = (const float*)d_in[0];
    float* out = (float*)d_out;

    cudaFuncSetAttribute(dist_mma_kernel,
                         cudaFuncAttributeMaxDynamicSharedMemorySize, DSMEM_BYTES);

    prep_kernel<<<N_PTS / 8, 256>>>(x);
    dist_mma_kernel<<<NTILE * (NTILE + 1) / 2, 256, DSMEM_BYTES>>>();
    merge_smooth_kernel<<<N_PTS, 128>>>(x, out);
}